// round 2
// baseline (speedup 1.0000x reference)
#include <cuda_runtime.h>
#include <cuda_bf16.h>
#include <cstddef>

// Problem constants
#define BB 4
#define SS 2048
#define DD 1024
#define HH 16
#define DKK 64
#define FF 4096
#define MM (BB*SS)          // 8192 rows

// ---------------------------------------------------------------------------
// Scratch (no allocations allowed -> __device__ globals)
// ---------------------------------------------------------------------------
__device__ float g_q   [(size_t)MM*DD];
__device__ float g_k   [(size_t)MM*DD];
__device__ float g_v   [(size_t)MM*DD];
__device__ float g_att [(size_t)MM*DD];
__device__ float g_proj[(size_t)MM*DD];
__device__ float g_x1  [(size_t)MM*DD];
__device__ float g_ff1 [(size_t)MM*FF];
__device__ float g_ff2 [(size_t)MM*DD];

// ---------------------------------------------------------------------------
// SGEMM: C[M,N] = A[M,K] @ W[K,N] + bias (optional ReLU)
// BM=BN=128, BK=8, 256 threads, 8x8 per-thread micro tile.
// M,N,K all divisible by tile sizes for every call in this problem.
// ---------------------------------------------------------------------------
__global__ __launch_bounds__(256) void sgemm_kernel(
    const float* __restrict__ A, const float* __restrict__ W,
    const float* __restrict__ bias, float* __restrict__ C,
    int M, int N, int K, int relu)
{
    __shared__ float As[8][128];
    __shared__ float Bs[8][128];

    const int tid = threadIdx.x;
    const int tr = tid / 16;          // 0..15
    const int tc = tid % 16;          // 0..15

    const int aRow = tid >> 1;        // 0..127
    const int aCol = (tid & 1) * 4;   // 0 or 4
    const int bRow = tid >> 5;        // 0..7
    const int bCol = (tid & 31) * 4;  // 0..124

    const float* Ab = A + (size_t)blockIdx.y * 128 * K;
    const float* Wb = W + (size_t)blockIdx.x * 128;

    float acc[8][8];
    #pragma unroll
    for (int i = 0; i < 8; i++)
        #pragma unroll
        for (int j = 0; j < 8; j++) acc[i][j] = 0.f;

    for (int k0 = 0; k0 < K; k0 += 8) {
        float4 a4 = *(const float4*)(Ab + (size_t)aRow * K + k0 + aCol);
        As[aCol + 0][aRow] = a4.x;
        As[aCol + 1][aRow] = a4.y;
        As[aCol + 2][aRow] = a4.z;
        As[aCol + 3][aRow] = a4.w;
        float4 b4 = *(const float4*)(Wb + (size_t)(k0 + bRow) * N + bCol);
        *(float4*)(&Bs[bRow][bCol]) = b4;
        __syncthreads();

        #pragma unroll
        for (int kk = 0; kk < 8; kk++) {
            float ar[8], br[8];
            #pragma unroll
            for (int i = 0; i < 8; i++) ar[i] = As[kk][tr * 8 + i];
            #pragma unroll
            for (int j = 0; j < 8; j++) br[j] = Bs[kk][tc * 8 + j];
            #pragma unroll
            for (int i = 0; i < 8; i++)
                #pragma unroll
                for (int j = 0; j < 8; j++) acc[i][j] += ar[i] * br[j];
        }
        __syncthreads();
    }

    const int colBase = blockIdx.x * 128 + tc * 8;
    #pragma unroll
    for (int i = 0; i < 8; i++) {
        const size_t row = (size_t)blockIdx.y * 128 + tr * 8 + i;
        float* crow = C + row * N + colBase;
        #pragma unroll
        for (int j = 0; j < 8; j += 4) {
            float4 o;
            o.x = acc[i][j + 0] + bias[colBase + j + 0];
            o.y = acc[i][j + 1] + bias[colBase + j + 1];
            o.z = acc[i][j + 2] + bias[colBase + j + 2];
            o.w = acc[i][j + 3] + bias[colBase + j + 3];
            if (relu) {
                o.x = fmaxf(o.x, 0.f); o.y = fmaxf(o.y, 0.f);
                o.z = fmaxf(o.z, 0.f); o.w = fmaxf(o.w, 0.f);
            }
            *(float4*)(crow + j) = o;
        }
    }
}

// ---------------------------------------------------------------------------
// Flash attention, fp32. One block = one (b,h, 64-row Q tile).
// Q/K/V are [B*S, D] with head h in columns [h*64, h*64+64).
// smem: Qs[64][65], KVs[64][65] (K then V reuse), Ss[64][64] stored [key][row].
// ---------------------------------------------------------------------------
#define ATT_SMEM_FLOATS (65*64 + 65*64 + 64*64)
#define ATT_SMEM_BYTES  (ATT_SMEM_FLOATS * 4)

__global__ __launch_bounds__(256) void attn_kernel(
    const float* __restrict__ Q, const float* __restrict__ K,
    const float* __restrict__ V, float* __restrict__ O)
{
    extern __shared__ float sm[];
    float* Qs  = sm;                 // [64][65]
    float* KVs = sm + 65 * 64;       // [64][65]
    float* Ss  = sm + 2 * 65 * 64;   // [64][64], layout [j][r]

    const int t  = threadIdx.x;
    const int q0 = blockIdx.x * 64;
    const int b  = blockIdx.y >> 4;  // / H
    const int h  = blockIdx.y & 15;  // % H
    const size_t base = (size_t)b * SS * DD + (size_t)h * 64;

    const int rl = t >> 2;           // load/output row (0..63)
    const int c0 = (t & 3) * 16;     // 16-wide column segment

    // Q tile load (scale folded into scores later)
    {
        const float* src = Q + base + (size_t)(q0 + rl) * DD + c0;
        #pragma unroll
        for (int i = 0; i < 16; i++) Qs[rl * 65 + c0 + i] = src[i];
    }

    const int r  = rl;               // phase B/C row
    const int cs = c0;
    const int ra = t & 63;           // phase A row
    const int js = (t >> 6) * 16;    // phase A key segment

    float m = -1e30f, l = 0.f;
    float acc[16];
    #pragma unroll
    for (int i = 0; i < 16; i++) acc[i] = 0.f;

    const int ntiles = blockIdx.x + 1;   // causal
    for (int kt = 0; kt < ntiles; kt++) {
        const int k0 = kt * 64;
        __syncthreads();
        // load K tile
        {
            const float* src = K + base + (size_t)(k0 + rl) * DD + c0;
            #pragma unroll
            for (int i = 0; i < 16; i++) KVs[rl * 65 + c0 + i] = src[i];
        }
        __syncthreads();
        // phase A: scores for (row ra, keys js..js+15)
        {
            float s[16];
            #pragma unroll
            for (int jj = 0; jj < 16; jj++) s[jj] = 0.f;
            for (int d = 0; d < 64; d++) {
                const float qd = Qs[ra * 65 + d];
                #pragma unroll
                for (int jj = 0; jj < 16; jj++)
                    s[jj] += qd * KVs[(js + jj) * 65 + d];
            }
            #pragma unroll
            for (int jj = 0; jj < 16; jj++) {
                const int j = js + jj;
                Ss[j * 64 + ra] = (k0 + j <= q0 + ra) ? s[jj] * 0.125f : -1e30f;
            }
        }
        __syncthreads();
        // load V tile (K done) + row max
        {
            const float* src = V + base + (size_t)(k0 + rl) * DD + c0;
            #pragma unroll
            for (int i = 0; i < 16; i++) KVs[rl * 65 + c0 + i] = src[i];
        }
        float mt = -1e30f;
        for (int j = 0; j < 64; j++) mt = fmaxf(mt, Ss[j * 64 + r]);
        const float mnew = fmaxf(m, mt);
        __syncthreads();
        // write p = exp(s - mnew) into own exclusive segment
        #pragma unroll
        for (int jj = 0; jj < 16; jj++) {
            const int j = cs + jj;
            Ss[j * 64 + r] = __expf(Ss[j * 64 + r] - mnew);
        }
        __syncthreads();
        // rescale + accumulate
        const float corr = __expf(m - mnew);
        float lsum = 0.f;
        for (int j = 0; j < 64; j++) lsum += Ss[j * 64 + r];
        l = l * corr + lsum;
        m = mnew;
        #pragma unroll
        for (int i = 0; i < 16; i++) acc[i] *= corr;
        for (int j = 0; j < 64; j++) {
            const float p = Ss[j * 64 + r];
            #pragma unroll
            for (int i = 0; i < 16; i++) acc[i] += p * KVs[j * 65 + cs + i];
        }
    }

    const float inv = 1.f / l;
    float* dst = O + base + (size_t)(q0 + r) * DD + cs;
    #pragma unroll
    for (int i = 0; i < 16; i++) dst[i] = acc[i] * inv;
}

// ---------------------------------------------------------------------------
// out = LayerNorm(x + y) * gamma + beta, one block per 1024-elem row
// ---------------------------------------------------------------------------
__device__ __forceinline__ float block_sum(float v, float* sh)
{
    const int lane = threadIdx.x & 31, w = threadIdx.x >> 5;
    #pragma unroll
    for (int o = 16; o; o >>= 1) v += __shfl_xor_sync(0xffffffffu, v, o);
    if (lane == 0) sh[w] = v;
    __syncthreads();
    float r = (lane < 8) ? sh[lane] : 0.f;
    #pragma unroll
    for (int o = 4; o; o >>= 1) r += __shfl_xor_sync(0xffffffffu, r, o);
    if (threadIdx.x == 0) sh[0] = r;
    __syncthreads();
    r = sh[0];
    __syncthreads();   // safe reuse of sh
    return r;
}

__global__ __launch_bounds__(256) void add_ln_kernel(
    const float* __restrict__ X, const float* __restrict__ Y,
    const float* __restrict__ g, const float* __restrict__ bta,
    float* __restrict__ out)
{
    __shared__ float sh[32];
    const size_t row = blockIdx.x;
    const int t = threadIdx.x;
    const float4 xv = ((const float4*)(X + row * DD))[t];
    const float4 yv = ((const float4*)(Y + row * DD))[t];
    float v0 = xv.x + yv.x, v1 = xv.y + yv.y, v2 = xv.z + yv.z, v3 = xv.w + yv.w;
    const float mean = block_sum(v0 + v1 + v2 + v3, sh) * (1.f / DD);
    const float d0 = v0 - mean, d1 = v1 - mean, d2 = v2 - mean, d3 = v3 - mean;
    const float var = block_sum(d0*d0 + d1*d1 + d2*d2 + d3*d3, sh) * (1.f / DD);
    const float inv = rsqrtf(var + 1e-5f);
    const float4 gv = ((const float4*)g)[t];
    const float4 bv = ((const float4*)bta)[t];
    float4 o;
    o.x = d0 * inv * gv.x + bv.x;
    o.y = d1 * inv * gv.y + bv.y;
    o.z = d2 * inv * gv.z + bv.z;
    o.w = d3 * inv * gv.w + bv.w;
    ((float4*)(out + row * DD))[t] = o;
}

// ---------------------------------------------------------------------------
// Launcher
// ---------------------------------------------------------------------------
extern "C" void kernel_launch(void* const* d_in, const int* in_sizes, int n_in,
                              void* d_out, int out_size)
{
    (void)in_sizes; (void)n_in; (void)out_size;
    const float* x  = (const float*)d_in[0];
    /* d_in[1] = mask (int32) — causality is static, unused */
    const float* Wq = (const float*)d_in[2];
    const float* bq = (const float*)d_in[3];
    const float* Wk = (const float*)d_in[4];
    const float* bk = (const float*)d_in[5];
    const float* Wv = (const float*)d_in[6];
    const float* bv = (const float*)d_in[7];
    const float* Wo = (const float*)d_in[8];
    const float* bo = (const float*)d_in[9];
    const float* g1 = (const float*)d_in[10];
    const float* b1 = (const float*)d_in[11];
    const float* W1 = (const float*)d_in[12];
    const float* c1 = (const float*)d_in[13];
    const float* W2 = (const float*)d_in[14];
    const float* c2 = (const float*)d_in[15];
    const float* g2 = (const float*)d_in[16];
    const float* b2 = (const float*)d_in[17];
    float* out = (float*)d_out;

    float *q, *k, *v, *att, *proj, *x1, *ff1, *ff2;
    cudaGetSymbolAddress((void**)&q,    g_q);
    cudaGetSymbolAddress((void**)&k,    g_k);
    cudaGetSymbolAddress((void**)&v,    g_v);
    cudaGetSymbolAddress((void**)&att,  g_att);
    cudaGetSymbolAddress((void**)&proj, g_proj);
    cudaGetSymbolAddress((void**)&x1,   g_x1);
    cudaGetSymbolAddress((void**)&ff1,  g_ff1);
    cudaGetSymbolAddress((void**)&ff2,  g_ff2);

    cudaFuncSetAttribute(attn_kernel,
                         cudaFuncAttributeMaxDynamicSharedMemorySize,
                         ATT_SMEM_BYTES);

    const dim3 blk(256);
    // QKV projections: [8192,1024] @ [1024,1024]
    const dim3 gD(DD / 128, MM / 128);
    sgemm_kernel<<<gD, blk>>>(x, Wq, bq, q, MM, DD, DD, 0);
    sgemm_kernel<<<gD, blk>>>(x, Wk, bk, k, MM, DD, DD, 0);
    sgemm_kernel<<<gD, blk>>>(x, Wv, bv, v, MM, DD, DD, 0);

    // attention
    attn_kernel<<<dim3(SS / 64, BB * HH), blk, ATT_SMEM_BYTES>>>(q, k, v, att);

    // output projection + residual LN
    sgemm_kernel<<<gD, blk>>>(att, Wo, bo, proj, MM, DD, DD, 0);
    add_ln_kernel<<<MM, blk>>>(x, proj, g1, b1, x1);

    // FFN
    sgemm_kernel<<<dim3(FF / 128, MM / 128), blk>>>(x1, W1, c1, ff1, MM, FF, DD, 1);
    sgemm_kernel<<<gD, blk>>>(ff1, W2, c2, ff2, MM, DD, FF, 0);
    add_ln_kernel<<<MM, blk>>>(x1, ff2, g2, b2, out);
}

// round 4
// speedup vs baseline: 1.4581x; 1.4581x over previous
#include <cuda_runtime.h>
#include <cuda_bf16.h>
#include <cstdint>
#include <cstddef>

// Problem constants
#define BB 4
#define SS 2048
#define DD 1024
#define HH 16
#define DKK 64
#define FF 4096
#define MM (BB*SS)          // 8192 rows

// ---------------------------------------------------------------------------
// Scratch (no allocations allowed -> __device__ globals)
// ---------------------------------------------------------------------------
__device__ float g_q   [(size_t)MM*DD];
__device__ float g_k   [(size_t)MM*DD];
__device__ float g_v   [(size_t)MM*DD];
__device__ float g_att [(size_t)MM*DD];
__device__ float g_proj[(size_t)MM*DD];
__device__ float g_x1  [(size_t)MM*DD];
__device__ float g_ff1 [(size_t)MM*FF];
__device__ float g_ff2 [(size_t)MM*DD];

// bf16 split operands (hi,hi,lo / hi,lo,hi K-expansion, K'' = 3K)
__device__ unsigned short g_ax  [(size_t)MM*3*DD];
__device__ unsigned short g_aatt[(size_t)MM*3*DD];
__device__ unsigned short g_ax1 [(size_t)MM*3*DD];
__device__ unsigned short g_aff1[(size_t)MM*3*FF];
__device__ unsigned short g_wq  [(size_t)DD*3*DD];
__device__ unsigned short g_wk  [(size_t)DD*3*DD];
__device__ unsigned short g_wv  [(size_t)DD*3*DD];
__device__ unsigned short g_wo  [(size_t)DD*3*DD];
__device__ unsigned short g_w1  [(size_t)FF*3*DD];   // [N=F, 3K=3*D]
__device__ unsigned short g_w2  [(size_t)DD*3*FF];   // [N=D, 3K=3*F]

// ---------------------------------------------------------------------------
// Helpers (family-portable PTX only: cp.async / ldmatrix / mma.sync)
// ---------------------------------------------------------------------------
__device__ __forceinline__ uint32_t smem_u32(const void* p) {
    uint32_t a;
    asm("{ .reg .u64 t; cvta.to.shared.u64 t, %1; cvt.u32.u64 %0, t; }"
        : "=r"(a) : "l"(p));
    return a;
}

__device__ __forceinline__ void cp16(uint32_t dst, const void* src) {
    asm volatile("cp.async.cg.shared.global [%0], [%1], 16;" :: "r"(dst), "l"(src));
}

#define CP_COMMIT() asm volatile("cp.async.commit_group;")
#define CP_WAIT2()  asm volatile("cp.async.wait_group 2;" ::: "memory")

#define LDSM4(r0, r1, r2, r3, addr) \
    asm volatile("ldmatrix.sync.aligned.m8n8.x4.shared.b16 {%0,%1,%2,%3}, [%4];" \
        : "=r"(r0), "=r"(r1), "=r"(r2), "=r"(r3) : "r"(addr))

#define MMA16816(d, a, b0v, b1v) \
    asm volatile("mma.sync.aligned.m16n8k16.row.col.f32.bf16.bf16.f32 " \
        "{%0,%1,%2,%3}, {%4,%5,%6,%7}, {%8,%9}, {%0,%1,%2,%3};" \
        : "+f"((d)[0]), "+f"((d)[1]), "+f"((d)[2]), "+f"((d)[3]) \
        : "r"((a)[0]), "r"((a)[1]), "r"((a)[2]), "r"((a)[3]), "r"(b0v), "r"(b1v))

// ---------------------------------------------------------------------------
// fp32 -> (hi,hi,lo) bf16 K-expansion for activations. A''[m, 3K].
// ---------------------------------------------------------------------------
__device__ __forceinline__ unsigned short f2bf_bits(float f) {
    __nv_bfloat16 h = __float2bfloat16(f);
    return *reinterpret_cast<unsigned short*>(&h);
}

__global__ __launch_bounds__(256) void convert_a_kernel(
    const float* __restrict__ X, unsigned short* __restrict__ A, int K)
{
    size_t idx = (size_t)blockIdx.x * blockDim.x + threadIdx.x;
    size_t total = (size_t)MM * K / 4;
    if (idx >= total) return;
    size_t e = idx * 4;
    size_t m = e / K;
    int k = (int)(e % K);
    float4 v = *(const float4*)(X + e);
    unsigned short h0 = f2bf_bits(v.x), h1 = f2bf_bits(v.y),
                   h2 = f2bf_bits(v.z), h3 = f2bf_bits(v.w);
    __nv_bfloat16 hb0 = *reinterpret_cast<__nv_bfloat16*>(&h0);
    __nv_bfloat16 hb1 = *reinterpret_cast<__nv_bfloat16*>(&h1);
    __nv_bfloat16 hb2 = *reinterpret_cast<__nv_bfloat16*>(&h2);
    __nv_bfloat16 hb3 = *reinterpret_cast<__nv_bfloat16*>(&h3);
    unsigned short l0 = f2bf_bits(v.x - __bfloat162float(hb0));
    unsigned short l1 = f2bf_bits(v.y - __bfloat162float(hb1));
    unsigned short l2 = f2bf_bits(v.z - __bfloat162float(hb2));
    unsigned short l3 = f2bf_bits(v.w - __bfloat162float(hb3));
    uint2 hp = make_uint2((uint32_t)h0 | ((uint32_t)h1 << 16),
                          (uint32_t)h2 | ((uint32_t)h3 << 16));
    uint2 lp = make_uint2((uint32_t)l0 | ((uint32_t)l1 << 16),
                          (uint32_t)l2 | ((uint32_t)l3 << 16));
    size_t ob = m * (size_t)(3 * K);
    *(uint2*)(A + ob + k)         = hp;   // hi
    *(uint2*)(A + ob + K + k)     = hp;   // hi
    *(uint2*)(A + ob + 2 * K + k) = lp;   // lo
}

// ---------------------------------------------------------------------------
// W[K,N] fp32 -> B''[N, 3K] bf16 with (hi, lo, hi) layout (transposed).
// ---------------------------------------------------------------------------
__global__ __launch_bounds__(256) void convert_w_kernel(
    const float* __restrict__ W, unsigned short* __restrict__ Bm, int K, int N)
{
    __shared__ float tile[32][33];
    const int n0 = blockIdx.x * 32;
    const int k0 = blockIdx.y * 32;
    for (int i = threadIdx.y; i < 32; i += 8)
        tile[i][threadIdx.x] = W[(size_t)(k0 + i) * N + n0 + threadIdx.x];
    __syncthreads();
    for (int i = threadIdx.y; i < 32; i += 8) {
        const int n = n0 + i;
        const int k = k0 + threadIdx.x;
        float x = tile[threadIdx.x][i];
        unsigned short h = f2bf_bits(x);
        __nv_bfloat16 hb = *reinterpret_cast<__nv_bfloat16*>(&h);
        unsigned short l = f2bf_bits(x - __bfloat162float(hb));
        size_t ob = (size_t)n * (3 * K);
        Bm[ob + k]         = h;   // hi
        Bm[ob + K + k]     = l;   // lo
        Bm[ob + 2 * K + k] = h;   // hi
    }
}

// ---------------------------------------------------------------------------
// mma.sync bf16 GEMM: C[M,N] = A''[M,K3] @ B''[N,K3]^T + bias (opt ReLU)
// BM=BN=128, BK=32, 3-stage cp.async pipeline, 256 threads (8 warps 2x4),
// warp tile 64x32 via m16n8k16. Smem rows padded to 80B -> ldmatrix
// conflict-free (r*80 mod 128 covers 8 distinct 16B banks).
// ---------------------------------------------------------------------------
#define BK 32
#define NSTAGE 3
#define ROWB 80                     // bytes per padded smem row (32 bf16 data)
#define B_OFF (128*ROWB)            // 10240 (B region within a stage)
#define STG_B (2*B_OFF)             // 20480 per stage
#define GEMM_SMEM (NSTAGE*STG_B)    // 61440

__global__ __launch_bounds__(256) void mma_gemm_kernel(
    const unsigned short* __restrict__ Au, const unsigned short* __restrict__ Bu,
    const float* __restrict__ bias, float* __restrict__ C,
    int N, int K3, int relu)
{
    extern __shared__ char smem[];
    const uint32_t sb = smem_u32(smem);
    const int tid = threadIdx.x;
    const int wid = tid >> 5, lane = tid & 31;
    const int wm = wid >> 2, wn = wid & 3;          // 2 x 4 warp grid
    const int mb = blockIdx.y, nb = blockIdx.x;

    // cp.async mapping: thread -> (row r0 and r0+64, 16B chunk cc) for A and B
    const int r0 = tid >> 2, cc = tid & 3;
    const unsigned short* aS = Au + ((size_t)(mb * 128) + r0) * K3 + cc * 8;
    const unsigned short* bS = Bu + ((size_t)(nb * 128) + r0) * K3 + cc * 8;
    const size_t rowskip = (size_t)64 * K3;
    const uint32_t dOff = (uint32_t)(r0 * ROWB + cc * 16);

    float acc[4][4][4];
    #pragma unroll
    for (int i = 0; i < 4; i++)
        #pragma unroll
        for (int j = 0; j < 4; j++)
            #pragma unroll
            for (int r = 0; r < 4; r++) acc[i][j][r] = 0.f;

    const int nc = K3 / BK;

    auto LOAD = [&](int s, int c) {
        const uint32_t d = sb + s * STG_B + dOff;
        const unsigned short* a = aS + (size_t)c * BK;
        const unsigned short* b = bS + (size_t)c * BK;
        cp16(d,                    a);
        cp16(d + 64 * ROWB,        a + rowskip);
        cp16(d + B_OFF,            b);
        cp16(d + B_OFF + 64*ROWB,  b + rowskip);
    };

    LOAD(0, 0); CP_COMMIT();
    LOAD(1, 1); CP_COMMIT();

    // ldmatrix per-lane address components
    const uint32_t aRow = (uint32_t)(wm * 64 + (lane & 15));
    const uint32_t aK   = ((lane >> 4) & 1) * 16;
    const uint32_t bRow = (uint32_t)(wn * 32 + ((lane >> 4) & 1) * 8 + (lane & 7));
    const uint32_t bK   = ((lane >> 3) & 1) * 16;

    for (int c = 0; c < nc; c++) {
        if (c + 2 < nc) LOAD((c + 2) % NSTAGE, c + 2);
        CP_COMMIT();
        CP_WAIT2();
        __syncthreads();
        const uint32_t base = sb + (c % NSTAGE) * STG_B;
        #pragma unroll
        for (int ks = 0; ks < 2; ks++) {
            uint32_t af[4][4], bf[2][4];
            #pragma unroll
            for (int mt = 0; mt < 4; mt++) {
                const uint32_t ad = base + (aRow + mt * 16) * ROWB + ks * 32 + aK;
                LDSM4(af[mt][0], af[mt][1], af[mt][2], af[mt][3], ad);
            }
            #pragma unroll
            for (int j = 0; j < 2; j++) {
                const uint32_t bd = base + B_OFF + (bRow + j * 16) * ROWB + ks * 32 + bK;
                LDSM4(bf[j][0], bf[j][1], bf[j][2], bf[j][3], bd);
            }
            #pragma unroll
            for (int mt = 0; mt < 4; mt++)
                #pragma unroll
                for (int nt = 0; nt < 4; nt++)
                    MMA16816(acc[mt][nt], af[mt],
                             bf[nt >> 1][(nt & 1) * 2], bf[nt >> 1][(nt & 1) * 2 + 1]);
        }
        __syncthreads();
    }

    // epilogue: C frag -> global, fused bias (+ReLU)
    const int row0 = mb * 128 + wm * 64 + (lane >> 2);
    const int col0 = nb * 128 + wn * 32 + (lane & 3) * 2;
    #pragma unroll
    for (int mt = 0; mt < 4; mt++) {
        const int r1 = row0 + mt * 16;
        const int r2 = r1 + 8;
        #pragma unroll
        for (int nt = 0; nt < 4; nt++) {
            const int cn = col0 + nt * 8;
            const float bx = __ldg(bias + cn), by = __ldg(bias + cn + 1);
            float2 o1 = make_float2(acc[mt][nt][0] + bx, acc[mt][nt][1] + by);
            float2 o2 = make_float2(acc[mt][nt][2] + bx, acc[mt][nt][3] + by);
            if (relu) {
                o1.x = fmaxf(o1.x, 0.f); o1.y = fmaxf(o1.y, 0.f);
                o2.x = fmaxf(o2.x, 0.f); o2.y = fmaxf(o2.y, 0.f);
            }
            *(float2*)(C + (size_t)r1 * N + cn) = o1;
            *(float2*)(C + (size_t)r2 * N + cn) = o2;
        }
    }
}

// ---------------------------------------------------------------------------
// Flash attention, fp32 (unchanged)
// ---------------------------------------------------------------------------
#define ATT_SMEM_FLOATS (65*64 + 65*64 + 64*64)
#define ATT_SMEM_BYTES  (ATT_SMEM_FLOATS * 4)

__global__ __launch_bounds__(256) void attn_kernel(
    const float* __restrict__ Q, const float* __restrict__ K,
    const float* __restrict__ V, float* __restrict__ O)
{
    extern __shared__ float sm[];
    float* Qs  = sm;
    float* KVs = sm + 65 * 64;
    float* Ss  = sm + 2 * 65 * 64;

    const int t  = threadIdx.x;
    const int q0 = blockIdx.x * 64;
    const int b  = blockIdx.y >> 4;
    const int h  = blockIdx.y & 15;
    const size_t base = (size_t)b * SS * DD + (size_t)h * 64;

    const int rl = t >> 2;
    const int c0 = (t & 3) * 16;

    {
        const float* src = Q + base + (size_t)(q0 + rl) * DD + c0;
        #pragma unroll
        for (int i = 0; i < 16; i++) Qs[rl * 65 + c0 + i] = src[i];
    }

    const int r  = rl;
    const int cs = c0;
    const int ra = t & 63;
    const int js = (t >> 6) * 16;

    float m = -1e30f, l = 0.f;
    float acc[16];
    #pragma unroll
    for (int i = 0; i < 16; i++) acc[i] = 0.f;

    const int ntiles = blockIdx.x + 1;
    for (int kt = 0; kt < ntiles; kt++) {
        const int k0 = kt * 64;
        __syncthreads();
        {
            const float* src = K + base + (size_t)(k0 + rl) * DD + c0;
            #pragma unroll
            for (int i = 0; i < 16; i++) KVs[rl * 65 + c0 + i] = src[i];
        }
        __syncthreads();
        {
            float s[16];
            #pragma unroll
            for (int jj = 0; jj < 16; jj++) s[jj] = 0.f;
            for (int d = 0; d < 64; d++) {
                const float qd = Qs[ra * 65 + d];
                #pragma unroll
                for (int jj = 0; jj < 16; jj++)
                    s[jj] += qd * KVs[(js + jj) * 65 + d];
            }
            #pragma unroll
            for (int jj = 0; jj < 16; jj++) {
                const int j = js + jj;
                Ss[j * 64 + ra] = (k0 + j <= q0 + ra) ? s[jj] * 0.125f : -1e30f;
            }
        }
        __syncthreads();
        {
            const float* src = V + base + (size_t)(k0 + rl) * DD + c0;
            #pragma unroll
            for (int i = 0; i < 16; i++) KVs[rl * 65 + c0 + i] = src[i];
        }
        float mt = -1e30f;
        for (int j = 0; j < 64; j++) mt = fmaxf(mt, Ss[j * 64 + r]);
        const float mnew = fmaxf(m, mt);
        __syncthreads();
        #pragma unroll
        for (int jj = 0; jj < 16; jj++) {
            const int j = cs + jj;
            Ss[j * 64 + r] = __expf(Ss[j * 64 + r] - mnew);
        }
        __syncthreads();
        const float corr = __expf(m - mnew);
        float lsum = 0.f;
        for (int j = 0; j < 64; j++) lsum += Ss[j * 64 + r];
        l = l * corr + lsum;
        m = mnew;
        #pragma unroll
        for (int i = 0; i < 16; i++) acc[i] *= corr;
        for (int j = 0; j < 64; j++) {
            const float p = Ss[j * 64 + r];
            #pragma unroll
            for (int i = 0; i < 16; i++) acc[i] += p * KVs[j * 65 + cs + i];
        }
    }

    const float inv = 1.f / l;
    float* dst = O + base + (size_t)(q0 + r) * DD + cs;
    #pragma unroll
    for (int i = 0; i < 16; i++) dst[i] = acc[i] * inv;
}

// ---------------------------------------------------------------------------
// out = LayerNorm(x + y) * gamma + beta
// ---------------------------------------------------------------------------
__device__ __forceinline__ float block_sum(float v, float* sh)
{
    const int lane = threadIdx.x & 31, w = threadIdx.x >> 5;
    #pragma unroll
    for (int o = 16; o; o >>= 1) v += __shfl_xor_sync(0xffffffffu, v, o);
    if (lane == 0) sh[w] = v;
    __syncthreads();
    float r = (lane < 8) ? sh[lane] : 0.f;
    #pragma unroll
    for (int o = 4; o; o >>= 1) r += __shfl_xor_sync(0xffffffffu, r, o);
    if (threadIdx.x == 0) sh[0] = r;
    __syncthreads();
    r = sh[0];
    __syncthreads();
    return r;
}

__global__ __launch_bounds__(256) void add_ln_kernel(
    const float* __restrict__ X, const float* __restrict__ Y,
    const float* __restrict__ g, const float* __restrict__ bta,
    float* __restrict__ out)
{
    __shared__ float sh[32];
    const size_t row = blockIdx.x;
    const int t = threadIdx.x;
    const float4 xv = ((const float4*)(X + row * DD))[t];
    const float4 yv = ((const float4*)(Y + row * DD))[t];
    float v0 = xv.x + yv.x, v1 = xv.y + yv.y, v2 = xv.z + yv.z, v3 = xv.w + yv.w;
    const float mean = block_sum(v0 + v1 + v2 + v3, sh) * (1.f / DD);
    const float d0 = v0 - mean, d1 = v1 - mean, d2 = v2 - mean, d3 = v3 - mean;
    const float var = block_sum(d0*d0 + d1*d1 + d2*d2 + d3*d3, sh) * (1.f / DD);
    const float inv = rsqrtf(var + 1e-5f);
    const float4 gv = ((const float4*)g)[t];
    const float4 bv = ((const float4*)bta)[t];
    float4 o;
    o.x = d0 * inv * gv.x + bv.x;
    o.y = d1 * inv * gv.y + bv.y;
    o.z = d2 * inv * gv.z + bv.z;
    o.w = d3 * inv * gv.w + bv.w;
    ((float4*)(out + row * DD))[t] = o;
}

// ---------------------------------------------------------------------------
// Launcher
// ---------------------------------------------------------------------------
extern "C" void kernel_launch(void* const* d_in, const int* in_sizes, int n_in,
                              void* d_out, int out_size)
{
    (void)in_sizes; (void)n_in; (void)out_size;
    const float* x  = (const float*)d_in[0];
    const float* Wq = (const float*)d_in[2];
    const float* bq = (const float*)d_in[3];
    const float* Wk = (const float*)d_in[4];
    const float* bk = (const float*)d_in[5];
    const float* Wv = (const float*)d_in[6];
    const float* bv = (const float*)d_in[7];
    const float* Wo = (const float*)d_in[8];
    const float* bo = (const float*)d_in[9];
    const float* g1 = (const float*)d_in[10];
    const float* b1 = (const float*)d_in[11];
    const float* W1 = (const float*)d_in[12];
    const float* c1 = (const float*)d_in[13];
    const float* W2 = (const float*)d_in[14];
    const float* c2 = (const float*)d_in[15];
    const float* g2 = (const float*)d_in[16];
    const float* b2 = (const float*)d_in[17];
    float* out = (float*)d_out;

    float *q, *k, *v, *att, *proj, *x1, *ff1, *ff2;
    cudaGetSymbolAddress((void**)&q,    g_q);
    cudaGetSymbolAddress((void**)&k,    g_k);
    cudaGetSymbolAddress((void**)&v,    g_v);
    cudaGetSymbolAddress((void**)&att,  g_att);
    cudaGetSymbolAddress((void**)&proj, g_proj);
    cudaGetSymbolAddress((void**)&x1,   g_x1);
    cudaGetSymbolAddress((void**)&ff1,  g_ff1);
    cudaGetSymbolAddress((void**)&ff2,  g_ff2);

    unsigned short *ax, *aatt, *ax1, *aff1, *wq2, *wk2, *wv2, *wo2, *w12, *w22;
    cudaGetSymbolAddress((void**)&ax,   g_ax);
    cudaGetSymbolAddress((void**)&aatt, g_aatt);
    cudaGetSymbolAddress((void**)&ax1,  g_ax1);
    cudaGetSymbolAddress((void**)&aff1, g_aff1);
    cudaGetSymbolAddress((void**)&wq2,  g_wq);
    cudaGetSymbolAddress((void**)&wk2,  g_wk);
    cudaGetSymbolAddress((void**)&wv2,  g_wv);
    cudaGetSymbolAddress((void**)&wo2,  g_wo);
    cudaGetSymbolAddress((void**)&w12,  g_w1);
    cudaGetSymbolAddress((void**)&w22,  g_w2);

    cudaFuncSetAttribute(attn_kernel,
                         cudaFuncAttributeMaxDynamicSharedMemorySize, ATT_SMEM_BYTES);
    cudaFuncSetAttribute(mma_gemm_kernel,
                         cudaFuncAttributeMaxDynamicSharedMemorySize, GEMM_SMEM);

    const dim3 blk(256);
    const dim3 wblk(32, 8);

    // Weight conversions (transpose + hi/lo split)
    convert_w_kernel<<<dim3(DD/32, DD/32), wblk>>>(Wq, wq2, DD, DD);
    convert_w_kernel<<<dim3(DD/32, DD/32), wblk>>>(Wk, wk2, DD, DD);
    convert_w_kernel<<<dim3(DD/32, DD/32), wblk>>>(Wv, wv2, DD, DD);
    convert_w_kernel<<<dim3(DD/32, DD/32), wblk>>>(Wo, wo2, DD, DD);
    convert_w_kernel<<<dim3(FF/32, DD/32), wblk>>>(W1, w12, DD, FF);
    convert_w_kernel<<<dim3(DD/32, FF/32), wblk>>>(W2, w22, FF, DD);

    // x -> A''
    convert_a_kernel<<<(int)(((size_t)MM*DD/4 + 255)/256), blk>>>(x, ax, DD);

    // QKV projections on tensor cores (mma.sync)
    const dim3 gD(DD/128, MM/128);
    mma_gemm_kernel<<<gD, blk, GEMM_SMEM>>>(ax, wq2, bq, q, DD, 3*DD, 0);
    mma_gemm_kernel<<<gD, blk, GEMM_SMEM>>>(ax, wk2, bk, k, DD, 3*DD, 0);
    mma_gemm_kernel<<<gD, blk, GEMM_SMEM>>>(ax, wv2, bv, v, DD, 3*DD, 0);

    // attention (fp32)
    attn_kernel<<<dim3(SS/64, BB*HH), blk, ATT_SMEM_BYTES>>>(q, k, v, att);

    // output projection + residual LN
    convert_a_kernel<<<(int)(((size_t)MM*DD/4 + 255)/256), blk>>>(att, aatt, DD);
    mma_gemm_kernel<<<gD, blk, GEMM_SMEM>>>(aatt, wo2, bo, proj, DD, 3*DD, 0);
    add_ln_kernel<<<MM, blk>>>(x, proj, g1, b1, x1);

    // FFN
    convert_a_kernel<<<(int)(((size_t)MM*DD/4 + 255)/256), blk>>>(x1, ax1, DD);
    mma_gemm_kernel<<<dim3(FF/128, MM/128), blk, GEMM_SMEM>>>(ax1, w12, c1, ff1, FF, 3*DD, 1);
    convert_a_kernel<<<(int)(((size_t)MM*FF/4 + 255)/256), blk>>>(ff1, aff1, FF);
    mma_gemm_kernel<<<gD, blk, GEMM_SMEM>>>(aff1, w22, c2, ff2, DD, 3*FF, 0);
    add_ln_kernel<<<MM, blk>>>(x1, ff2, g2, b2, out);
}

// round 5
// speedup vs baseline: 3.3532x; 2.2998x over previous
#include <cuda_runtime.h>
#include <cuda_bf16.h>
#include <cstdint>
#include <cstddef>

// Problem constants
#define BB 4
#define SS 2048
#define DD 1024
#define HH 16
#define DKK 64
#define FF 4096
#define MM (BB*SS)          // 8192 rows

// ---------------------------------------------------------------------------
// Scratch (no allocations allowed -> __device__ globals)
// ---------------------------------------------------------------------------
__device__ float g_q   [(size_t)MM*DD];
__device__ float g_k   [(size_t)MM*DD];
__device__ float g_v   [(size_t)MM*DD];
__device__ float g_proj[(size_t)MM*DD];
__device__ float g_x1  [(size_t)MM*DD];
__device__ float g_ff1 [(size_t)MM*FF];
__device__ float g_ff2 [(size_t)MM*DD];

// bf16 split operands (hi,hi,lo / hi,lo,hi K-expansion, K'' = 3K)
__device__ unsigned short g_ax  [(size_t)MM*3*DD];
__device__ unsigned short g_aatt[(size_t)MM*3*DD];   // written by attention epilogue
__device__ unsigned short g_ax1 [(size_t)MM*3*DD];
__device__ unsigned short g_aff1[(size_t)MM*3*FF];
__device__ unsigned short g_wq  [(size_t)DD*3*DD];
__device__ unsigned short g_wk  [(size_t)DD*3*DD];
__device__ unsigned short g_wv  [(size_t)DD*3*DD];
__device__ unsigned short g_wo  [(size_t)DD*3*DD];
__device__ unsigned short g_w1  [(size_t)FF*3*DD];   // [N=F, 3K=3*D]
__device__ unsigned short g_w2  [(size_t)DD*3*FF];   // [N=D, 3K=3*F]

// ---------------------------------------------------------------------------
// Helpers (family-portable PTX only: cp.async / ldmatrix / mma.sync)
// ---------------------------------------------------------------------------
__device__ __forceinline__ uint32_t smem_u32(const void* p) {
    uint32_t a;
    asm("{ .reg .u64 t; cvta.to.shared.u64 t, %1; cvt.u32.u64 %0, t; }"
        : "=r"(a) : "l"(p));
    return a;
}

__device__ __forceinline__ void cp16(uint32_t dst, const void* src) {
    asm volatile("cp.async.cg.shared.global [%0], [%1], 16;" :: "r"(dst), "l"(src));
}

#define CP_COMMIT() asm volatile("cp.async.commit_group;")
#define CP_WAIT2()  asm volatile("cp.async.wait_group 2;" ::: "memory")

#define LDSM4(r0, r1, r2, r3, addr) \
    asm volatile("ldmatrix.sync.aligned.m8n8.x4.shared.b16 {%0,%1,%2,%3}, [%4];" \
        : "=r"(r0), "=r"(r1), "=r"(r2), "=r"(r3) : "r"(addr))

#define LDSM4T(r0, r1, r2, r3, addr) \
    asm volatile("ldmatrix.sync.aligned.m8n8.x4.trans.shared.b16 {%0,%1,%2,%3}, [%4];" \
        : "=r"(r0), "=r"(r1), "=r"(r2), "=r"(r3) : "r"(addr))

#define MMA16816(d, a, b0v, b1v) \
    asm volatile("mma.sync.aligned.m16n8k16.row.col.f32.bf16.bf16.f32 " \
        "{%0,%1,%2,%3}, {%4,%5,%6,%7}, {%8,%9}, {%0,%1,%2,%3};" \
        : "+f"((d)[0]), "+f"((d)[1]), "+f"((d)[2]), "+f"((d)[3]) \
        : "r"((a)[0]), "r"((a)[1]), "r"((a)[2]), "r"((a)[3]), "r"(b0v), "r"(b1v))

__device__ __forceinline__ unsigned short f2bf_bits(float f) {
    __nv_bfloat16 h = __float2bfloat16(f);
    return *reinterpret_cast<unsigned short*>(&h);
}
__device__ __forceinline__ void bfsplit(float x, unsigned short& h, unsigned short& l) {
    h = f2bf_bits(x);
    __nv_bfloat16 hb = *reinterpret_cast<__nv_bfloat16*>(&h);
    l = f2bf_bits(x - __bfloat162float(hb));
}

// ---------------------------------------------------------------------------
// fp32 -> (hi,hi,lo) bf16 K-expansion for activations. A''[m, 3K].
// ---------------------------------------------------------------------------
__global__ __launch_bounds__(256) void convert_a_kernel(
    const float* __restrict__ X, unsigned short* __restrict__ A, int K)
{
    size_t idx = (size_t)blockIdx.x * blockDim.x + threadIdx.x;
    size_t total = (size_t)MM * K / 4;
    if (idx >= total) return;
    size_t e = idx * 4;
    size_t m = e / K;
    int k = (int)(e % K);
    float4 v = *(const float4*)(X + e);
    unsigned short h0, h1, h2, h3, l0, l1, l2, l3;
    bfsplit(v.x, h0, l0); bfsplit(v.y, h1, l1);
    bfsplit(v.z, h2, l2); bfsplit(v.w, h3, l3);
    uint2 hp = make_uint2((uint32_t)h0 | ((uint32_t)h1 << 16),
                          (uint32_t)h2 | ((uint32_t)h3 << 16));
    uint2 lp = make_uint2((uint32_t)l0 | ((uint32_t)l1 << 16),
                          (uint32_t)l2 | ((uint32_t)l3 << 16));
    size_t ob = m * (size_t)(3 * K);
    *(uint2*)(A + ob + k)         = hp;   // hi
    *(uint2*)(A + ob + K + k)     = hp;   // hi
    *(uint2*)(A + ob + 2 * K + k) = lp;   // lo
}

// ---------------------------------------------------------------------------
// W[K,N] fp32 -> B''[N, 3K] bf16 with (hi, lo, hi) layout (transposed).
// ---------------------------------------------------------------------------
__global__ __launch_bounds__(256) void convert_w_kernel(
    const float* __restrict__ W, unsigned short* __restrict__ Bm, int K, int N)
{
    __shared__ float tile[32][33];
    const int n0 = blockIdx.x * 32;
    const int k0 = blockIdx.y * 32;
    for (int i = threadIdx.y; i < 32; i += 8)
        tile[i][threadIdx.x] = W[(size_t)(k0 + i) * N + n0 + threadIdx.x];
    __syncthreads();
    for (int i = threadIdx.y; i < 32; i += 8) {
        const int n = n0 + i;
        const int k = k0 + threadIdx.x;
        unsigned short h, l;
        bfsplit(tile[threadIdx.x][i], h, l);
        size_t ob = (size_t)n * (3 * K);
        Bm[ob + k]         = h;   // hi
        Bm[ob + K + k]     = l;   // lo
        Bm[ob + 2 * K + k] = h;   // hi
    }
}

// ---------------------------------------------------------------------------
// mma.sync bf16 GEMM: C[M,N] = A''[M,K3] @ B''[N,K3]^T + bias (opt ReLU)
// BM=BN=128, BK=32, 3-stage cp.async pipeline, 256 threads (8 warps 2x4).
// ---------------------------------------------------------------------------
#define BK 32
#define NSTAGE 3
#define ROWB 80
#define B_OFF (128*ROWB)
#define STG_B (2*B_OFF)
#define GEMM_SMEM (NSTAGE*STG_B)    // 61440

__global__ __launch_bounds__(256) void mma_gemm_kernel(
    const unsigned short* __restrict__ Au, const unsigned short* __restrict__ Bu,
    const float* __restrict__ bias, float* __restrict__ C,
    int N, int K3, int relu)
{
    extern __shared__ char smem[];
    const uint32_t sb = smem_u32(smem);
    const int tid = threadIdx.x;
    const int wid = tid >> 5, lane = tid & 31;
    const int wm = wid >> 2, wn = wid & 3;
    const int mb = blockIdx.y, nb = blockIdx.x;

    const int r0 = tid >> 2, cc = tid & 3;
    const unsigned short* aS = Au + ((size_t)(mb * 128) + r0) * K3 + cc * 8;
    const unsigned short* bS = Bu + ((size_t)(nb * 128) + r0) * K3 + cc * 8;
    const size_t rowskip = (size_t)64 * K3;
    const uint32_t dOff = (uint32_t)(r0 * ROWB + cc * 16);

    float acc[4][4][4];
    #pragma unroll
    for (int i = 0; i < 4; i++)
        #pragma unroll
        for (int j = 0; j < 4; j++)
            #pragma unroll
            for (int r = 0; r < 4; r++) acc[i][j][r] = 0.f;

    const int nc = K3 / BK;

    auto LOAD = [&](int s, int c) {
        const uint32_t d = sb + s * STG_B + dOff;
        const unsigned short* a = aS + (size_t)c * BK;
        const unsigned short* b = bS + (size_t)c * BK;
        cp16(d,                    a);
        cp16(d + 64 * ROWB,        a + rowskip);
        cp16(d + B_OFF,            b);
        cp16(d + B_OFF + 64*ROWB,  b + rowskip);
    };

    LOAD(0, 0); CP_COMMIT();
    LOAD(1, 1); CP_COMMIT();

    const uint32_t aRow = (uint32_t)(wm * 64 + (lane & 15));
    const uint32_t aK   = ((lane >> 4) & 1) * 16;
    const uint32_t bRow = (uint32_t)(wn * 32 + ((lane >> 4) & 1) * 8 + (lane & 7));
    const uint32_t bK   = ((lane >> 3) & 1) * 16;

    for (int c = 0; c < nc; c++) {
        if (c + 2 < nc) LOAD((c + 2) % NSTAGE, c + 2);
        CP_COMMIT();
        CP_WAIT2();
        __syncthreads();
        const uint32_t base = sb + (c % NSTAGE) * STG_B;
        #pragma unroll
        for (int ks = 0; ks < 2; ks++) {
            uint32_t af[4][4], bf[2][4];
            #pragma unroll
            for (int mt = 0; mt < 4; mt++) {
                const uint32_t ad = base + (aRow + mt * 16) * ROWB + ks * 32 + aK;
                LDSM4(af[mt][0], af[mt][1], af[mt][2], af[mt][3], ad);
            }
            #pragma unroll
            for (int j = 0; j < 2; j++) {
                const uint32_t bd = base + B_OFF + (bRow + j * 16) * ROWB + ks * 32 + bK;
                LDSM4(bf[j][0], bf[j][1], bf[j][2], bf[j][3], bd);
            }
            #pragma unroll
            for (int mt = 0; mt < 4; mt++)
                #pragma unroll
                for (int nt = 0; nt < 4; nt++)
                    MMA16816(acc[mt][nt], af[mt],
                             bf[nt >> 1][(nt & 1) * 2], bf[nt >> 1][(nt & 1) * 2 + 1]);
        }
        __syncthreads();
    }

    const int row0 = mb * 128 + wm * 64 + (lane >> 2);
    const int col0 = nb * 128 + wn * 32 + (lane & 3) * 2;
    #pragma unroll
    for (int mt = 0; mt < 4; mt++) {
        const int r1 = row0 + mt * 16;
        const int r2 = r1 + 8;
        #pragma unroll
        for (int nt = 0; nt < 4; nt++) {
            const int cn = col0 + nt * 8;
            const float bx = __ldg(bias + cn), by = __ldg(bias + cn + 1);
            float2 o1 = make_float2(acc[mt][nt][0] + bx, acc[mt][nt][1] + by);
            float2 o2 = make_float2(acc[mt][nt][2] + bx, acc[mt][nt][3] + by);
            if (relu) {
                o1.x = fmaxf(o1.x, 0.f); o1.y = fmaxf(o1.y, 0.f);
                o2.x = fmaxf(o2.x, 0.f); o2.y = fmaxf(o2.y, 0.f);
            }
            *(float2*)(C + (size_t)r1 * N + cn) = o1;
            *(float2*)(C + (size_t)r2 * N + cn) = o2;
        }
    }
}

// ---------------------------------------------------------------------------
// Tensor-core flash attention (split bf16, fp32 softmax).
// Block = 64 Q rows of one (b,h); 4 warps, each warp 16 rows.
// Q''/K'' smem rows: [hi(64) | {hi|lo}(64) | {lo|hi}(64)] bf16, 400B padded.
// V stored as Vhi/Vlo [64 key][64 d] bf16, 144B padded rows, read via
// ldmatrix.trans. P fragments feed PV mma directly from registers (FA2).
// Epilogue writes split A'' (hi,hi,lo) straight into g_aatt for the Wo GEMM.
// ---------------------------------------------------------------------------
#define AQROWB 400                      // 192 bf16 data + 8 pad
#define AVROWB 144                      // 64 bf16 data + 8 pad
#define ATT2_SMEM (2*64*AQROWB + 2*64*AVROWB)   // 69632

__global__ __launch_bounds__(128) void attn_tc_kernel(
    const float* __restrict__ Q, const float* __restrict__ K,
    const float* __restrict__ V, unsigned short* __restrict__ Aout)
{
    extern __shared__ char sm8[];
    char* Qs = sm8;
    char* Ks = Qs + 64 * AQROWB;
    char* Vh = Ks + 64 * AQROWB;
    char* Vl = Vh + 64 * AVROWB;
    const uint32_t qsb = smem_u32(Qs), ksb = smem_u32(Ks);
    const uint32_t vhb = smem_u32(Vh), vlb = smem_u32(Vl);

    const int tid = threadIdx.x, wid = tid >> 5, lane = tid & 31;
    const int q0 = blockIdx.x * 64;
    const int b = blockIdx.y >> 4, h = blockIdx.y & 15;
    const size_t base = (size_t)b * SS * DD + (size_t)h * 64;

    // ---- load Q tile (scale 1/8 folded in), split to smem ----
    {
        const int r = tid >> 1, c0 = (tid & 1) * 32;
        const float* src = Q + base + (size_t)(q0 + r) * DD + c0;
        unsigned short* drow = (unsigned short*)(Qs + r * AQROWB);
        #pragma unroll
        for (int i = 0; i < 8; i++) {
            float4 v4 = *(const float4*)(src + i * 4);
            float vv[4] = {v4.x * 0.125f, v4.y * 0.125f, v4.z * 0.125f, v4.w * 0.125f};
            #pragma unroll
            for (int j = 0; j < 4; j++) {
                unsigned short hh, ll;
                bfsplit(vv[j], hh, ll);
                const int c = c0 + i * 4 + j;
                drow[c] = hh; drow[64 + c] = hh; drow[128 + c] = ll;
            }
        }
    }
    __syncthreads();

    // ---- Q fragments in registers (12 k-steps x 4 regs) ----
    uint32_t qf[12][4];
    {
        const uint32_t ab = qsb + (wid * 16 + (lane & 15)) * AQROWB + ((lane >> 4) & 1) * 16;
        #pragma unroll
        for (int ks = 0; ks < 12; ks++)
            LDSM4(qf[ks][0], qf[ks][1], qf[ks][2], qf[ks][3], ab + ks * 32);
    }

    const uint32_t bRow = ((lane >> 4) & 1) * 8 + (lane & 7);
    const uint32_t bK   = ((lane >> 3) & 1) * 16;
    const uint32_t vLn  = (lane & 15);
    const uint32_t vCo  = ((lane >> 4) & 1) * 16;

    float O[8][4];
    #pragma unroll
    for (int j = 0; j < 8; j++)
        #pragma unroll
        for (int r = 0; r < 4; r++) O[j][r] = 0.f;
    float m0 = -1e30f, m1 = -1e30f, l0 = 0.f, l1 = 0.f;

    const int r0l = wid * 16 + (lane >> 2);
    const int r1l = r0l + 8;

    for (int kt = 0; kt <= blockIdx.x; kt++) {
        const int k0 = kt * 64;
        __syncthreads();
        // ---- load K (split) and V (hi/lo) tiles ----
        {
            const int r = tid >> 1, c0 = (tid & 1) * 32;
            const float* ksrc = K + base + (size_t)(k0 + r) * DD + c0;
            const float* vsrc = V + base + (size_t)(k0 + r) * DD + c0;
            unsigned short* kr = (unsigned short*)(Ks + r * AQROWB);
            unsigned short* vhr = (unsigned short*)(Vh + r * AVROWB);
            unsigned short* vlr = (unsigned short*)(Vl + r * AVROWB);
            #pragma unroll
            for (int i = 0; i < 8; i++) {
                float4 kv = *(const float4*)(ksrc + i * 4);
                float4 vv = *(const float4*)(vsrc + i * 4);
                const float ka[4] = {kv.x, kv.y, kv.z, kv.w};
                const float va[4] = {vv.x, vv.y, vv.z, vv.w};
                #pragma unroll
                for (int j = 0; j < 4; j++) {
                    const int c = c0 + i * 4 + j;
                    unsigned short hh, ll;
                    bfsplit(ka[j], hh, ll);
                    kr[c] = hh; kr[64 + c] = ll; kr[128 + c] = hh;
                    bfsplit(va[j], hh, ll);
                    vhr[c] = hh; vlr[c] = ll;
                }
            }
        }
        __syncthreads();

        // ---- S = Q'' K''^T ----
        float s[8][4];
        #pragma unroll
        for (int j = 0; j < 8; j++)
            #pragma unroll
            for (int r = 0; r < 4; r++) s[j][r] = 0.f;
        #pragma unroll
        for (int ks = 0; ks < 12; ks++) {
            #pragma unroll
            for (int j16 = 0; j16 < 4; j16++) {
                uint32_t kf0, kf1, kf2, kf3;
                LDSM4(kf0, kf1, kf2, kf3,
                      ksb + (j16 * 16 + bRow) * AQROWB + ks * 32 + bK);
                MMA16816(s[2 * j16],     qf[ks], kf0, kf1);
                MMA16816(s[2 * j16 + 1], qf[ks], kf2, kf3);
            }
        }

        // ---- causal mask (diagonal tile only) ----
        if (kt == (int)blockIdx.x) {
            #pragma unroll
            for (int j = 0; j < 8; j++) {
                const int c = j * 8 + 2 * (lane & 3);
                if (c     > r0l) s[j][0] = -1e30f;
                if (c + 1 > r0l) s[j][1] = -1e30f;
                if (c     > r1l) s[j][2] = -1e30f;
                if (c + 1 > r1l) s[j][3] = -1e30f;
            }
        }

        // ---- online softmax ----
        float mx0 = -1e30f, mx1 = -1e30f;
        #pragma unroll
        for (int j = 0; j < 8; j++) {
            mx0 = fmaxf(mx0, fmaxf(s[j][0], s[j][1]));
            mx1 = fmaxf(mx1, fmaxf(s[j][2], s[j][3]));
        }
        mx0 = fmaxf(mx0, __shfl_xor_sync(0xffffffffu, mx0, 1));
        mx0 = fmaxf(mx0, __shfl_xor_sync(0xffffffffu, mx0, 2));
        mx1 = fmaxf(mx1, __shfl_xor_sync(0xffffffffu, mx1, 1));
        mx1 = fmaxf(mx1, __shfl_xor_sync(0xffffffffu, mx1, 2));
        const float mn0 = fmaxf(m0, mx0), mn1 = fmaxf(m1, mx1);
        const float cr0 = __expf(m0 - mn0), cr1 = __expf(m1 - mn1);
        m0 = mn0; m1 = mn1;
        float sum0 = 0.f, sum1 = 0.f;
        #pragma unroll
        for (int j = 0; j < 8; j++) {
            s[j][0] = __expf(s[j][0] - mn0);
            s[j][1] = __expf(s[j][1] - mn0);
            s[j][2] = __expf(s[j][2] - mn1);
            s[j][3] = __expf(s[j][3] - mn1);
            sum0 += s[j][0] + s[j][1];
            sum1 += s[j][2] + s[j][3];
        }
        sum0 += __shfl_xor_sync(0xffffffffu, sum0, 1);
        sum0 += __shfl_xor_sync(0xffffffffu, sum0, 2);
        sum1 += __shfl_xor_sync(0xffffffffu, sum1, 1);
        sum1 += __shfl_xor_sync(0xffffffffu, sum1, 2);
        l0 = l0 * cr0 + sum0;
        l1 = l1 * cr1 + sum1;
        #pragma unroll
        for (int j = 0; j < 8; j++) {
            O[j][0] *= cr0; O[j][1] *= cr0;
            O[j][2] *= cr1; O[j][3] *= cr1;
        }

        // ---- P -> bf16 hi/lo A-fragments (register-only, FA2 trick) ----
        uint32_t phi[4][4], plo[4][4];
        #pragma unroll
        for (int ks2 = 0; ks2 < 4; ks2++) {
            const int j0 = 2 * ks2, j1 = j0 + 1;
            unsigned short h00, l00, h01, l01, h10, l10, h11, l11;
            bfsplit(s[j0][0], h00, l00); bfsplit(s[j0][1], h01, l01);
            phi[ks2][0] = (uint32_t)h00 | ((uint32_t)h01 << 16);
            plo[ks2][0] = (uint32_t)l00 | ((uint32_t)l01 << 16);
            bfsplit(s[j0][2], h10, l10); bfsplit(s[j0][3], h11, l11);
            phi[ks2][1] = (uint32_t)h10 | ((uint32_t)h11 << 16);
            plo[ks2][1] = (uint32_t)l10 | ((uint32_t)l11 << 16);
            bfsplit(s[j1][0], h00, l00); bfsplit(s[j1][1], h01, l01);
            phi[ks2][2] = (uint32_t)h00 | ((uint32_t)h01 << 16);
            plo[ks2][2] = (uint32_t)l00 | ((uint32_t)l01 << 16);
            bfsplit(s[j1][2], h10, l10); bfsplit(s[j1][3], h11, l11);
            phi[ks2][3] = (uint32_t)h10 | ((uint32_t)h11 << 16);
            plo[ks2][3] = (uint32_t)l10 | ((uint32_t)l11 << 16);
        }

        // ---- O += Phi*Vhi + Phi*Vlo + Plo*Vhi ----
        #pragma unroll
        for (int ks2 = 0; ks2 < 4; ks2++) {
            const uint32_t rowOff = (ks2 * 16 + vLn);
            #pragma unroll
            for (int dj = 0; dj < 4; dj++) {
                uint32_t vh0, vh1, vh2, vh3, vl0, vl1, vl2, vl3;
                LDSM4T(vh0, vh1, vh2, vh3, vhb + rowOff * AVROWB + dj * 32 + vCo);
                LDSM4T(vl0, vl1, vl2, vl3, vlb + rowOff * AVROWB + dj * 32 + vCo);
                MMA16816(O[2 * dj],     phi[ks2], vh0, vh1);
                MMA16816(O[2 * dj + 1], phi[ks2], vh2, vh3);
                MMA16816(O[2 * dj],     phi[ks2], vl0, vl1);
                MMA16816(O[2 * dj + 1], phi[ks2], vl2, vl3);
                MMA16816(O[2 * dj],     plo[ks2], vh0, vh1);
                MMA16816(O[2 * dj + 1], plo[ks2], vh2, vh3);
            }
        }
    }

    // ---- epilogue: O/l -> split A'' rows of g_aatt ----
    const float inv0 = 1.f / l0, inv1 = 1.f / l1;
    const size_t m0g = (size_t)b * SS + (q0 + r0l);
    const size_t m1g = m0g + 8;
    const int cb = h * 64 + 2 * (lane & 3);
    unsigned short* out0 = Aout + m0g * (size_t)(3 * DD) + cb;
    unsigned short* out1 = Aout + m1g * (size_t)(3 * DD) + cb;
    #pragma unroll
    for (int j = 0; j < 8; j++) {
        const int d = j * 8;
        unsigned short ha, la, hb2, lb2;
        bfsplit(O[j][0] * inv0, ha, la);
        bfsplit(O[j][1] * inv0, hb2, lb2);
        uint32_t hp = (uint32_t)ha | ((uint32_t)hb2 << 16);
        uint32_t lp = (uint32_t)la | ((uint32_t)lb2 << 16);
        *(uint32_t*)(out0 + d)            = hp;
        *(uint32_t*)(out0 + DD + d)       = hp;
        *(uint32_t*)(out0 + 2 * DD + d)   = lp;
        bfsplit(O[j][2] * inv1, ha, la);
        bfsplit(O[j][3] * inv1, hb2, lb2);
        hp = (uint32_t)ha | ((uint32_t)hb2 << 16);
        lp = (uint32_t)la | ((uint32_t)lb2 << 16);
        *(uint32_t*)(out1 + d)            = hp;
        *(uint32_t*)(out1 + DD + d)       = hp;
        *(uint32_t*)(out1 + 2 * DD + d)   = lp;
    }
}

// ---------------------------------------------------------------------------
// out = LayerNorm(x + y) * gamma + beta
// ---------------------------------------------------------------------------
__device__ __forceinline__ float block_sum(float v, float* sh)
{
    const int lane = threadIdx.x & 31, w = threadIdx.x >> 5;
    #pragma unroll
    for (int o = 16; o; o >>= 1) v += __shfl_xor_sync(0xffffffffu, v, o);
    if (lane == 0) sh[w] = v;
    __syncthreads();
    float r = (lane < 8) ? sh[lane] : 0.f;
    #pragma unroll
    for (int o = 4; o; o >>= 1) r += __shfl_xor_sync(0xffffffffu, r, o);
    if (threadIdx.x == 0) sh[0] = r;
    __syncthreads();
    r = sh[0];
    __syncthreads();
    return r;
}

__global__ __launch_bounds__(256) void add_ln_kernel(
    const float* __restrict__ X, const float* __restrict__ Y,
    const float* __restrict__ g, const float* __restrict__ bta,
    float* __restrict__ out)
{
    __shared__ float sh[32];
    const size_t row = blockIdx.x;
    const int t = threadIdx.x;
    const float4 xv = ((const float4*)(X + row * DD))[t];
    const float4 yv = ((const float4*)(Y + row * DD))[t];
    float v0 = xv.x + yv.x, v1 = xv.y + yv.y, v2 = xv.z + yv.z, v3 = xv.w + yv.w;
    const float mean = block_sum(v0 + v1 + v2 + v3, sh) * (1.f / DD);
    const float d0 = v0 - mean, d1 = v1 - mean, d2 = v2 - mean, d3 = v3 - mean;
    const float var = block_sum(d0*d0 + d1*d1 + d2*d2 + d3*d3, sh) * (1.f / DD);
    const float inv = rsqrtf(var + 1e-5f);
    const float4 gv = ((const float4*)g)[t];
    const float4 bv = ((const float4*)bta)[t];
    float4 o;
    o.x = d0 * inv * gv.x + bv.x;
    o.y = d1 * inv * gv.y + bv.y;
    o.z = d2 * inv * gv.z + bv.z;
    o.w = d3 * inv * gv.w + bv.w;
    ((float4*)(out + row * DD))[t] = o;
}

// ---------------------------------------------------------------------------
// Launcher. Launch #5 (0-indexed) is the Wq GEMM so ncu -s 5 -c 1 profiles it.
// ---------------------------------------------------------------------------
extern "C" void kernel_launch(void* const* d_in, const int* in_sizes, int n_in,
                              void* d_out, int out_size)
{
    (void)in_sizes; (void)n_in; (void)out_size;
    const float* x  = (const float*)d_in[0];
    const float* Wq = (const float*)d_in[2];
    const float* bq = (const float*)d_in[3];
    const float* Wk = (const float*)d_in[4];
    const float* bk = (const float*)d_in[5];
    const float* Wv = (const float*)d_in[6];
    const float* bv = (const float*)d_in[7];
    const float* Wo = (const float*)d_in[8];
    const float* bo = (const float*)d_in[9];
    const float* g1 = (const float*)d_in[10];
    const float* b1 = (const float*)d_in[11];
    const float* W1 = (const float*)d_in[12];
    const float* c1 = (const float*)d_in[13];
    const float* W2 = (const float*)d_in[14];
    const float* c2 = (const float*)d_in[15];
    const float* g2 = (const float*)d_in[16];
    const float* b2 = (const float*)d_in[17];
    float* out = (float*)d_out;

    float *q, *k, *v, *proj, *x1, *ff1, *ff2;
    cudaGetSymbolAddress((void**)&q,    g_q);
    cudaGetSymbolAddress((void**)&k,    g_k);
    cudaGetSymbolAddress((void**)&v,    g_v);
    cudaGetSymbolAddress((void**)&proj, g_proj);
    cudaGetSymbolAddress((void**)&x1,   g_x1);
    cudaGetSymbolAddress((void**)&ff1,  g_ff1);
    cudaGetSymbolAddress((void**)&ff2,  g_ff2);

    unsigned short *ax, *aatt, *ax1, *aff1, *wq2, *wk2, *wv2, *wo2, *w12, *w22;
    cudaGetSymbolAddress((void**)&ax,   g_ax);
    cudaGetSymbolAddress((void**)&aatt, g_aatt);
    cudaGetSymbolAddress((void**)&ax1,  g_ax1);
    cudaGetSymbolAddress((void**)&aff1, g_aff1);
    cudaGetSymbolAddress((void**)&wq2,  g_wq);
    cudaGetSymbolAddress((void**)&wk2,  g_wk);
    cudaGetSymbolAddress((void**)&wv2,  g_wv);
    cudaGetSymbolAddress((void**)&wo2,  g_wo);
    cudaGetSymbolAddress((void**)&w12,  g_w1);
    cudaGetSymbolAddress((void**)&w22,  g_w2);

    cudaFuncSetAttribute(mma_gemm_kernel,
                         cudaFuncAttributeMaxDynamicSharedMemorySize, GEMM_SMEM);
    cudaFuncSetAttribute(attn_tc_kernel,
                         cudaFuncAttributeMaxDynamicSharedMemorySize, ATT2_SMEM);

    const dim3 blk(256);
    const dim3 wblk(32, 8);
    const dim3 gD(DD/128, MM/128);

    // #0-3: QKV/O weight converts, #4: x -> A''
    convert_w_kernel<<<dim3(DD/32, DD/32), wblk>>>(Wq, wq2, DD, DD);
    convert_w_kernel<<<dim3(DD/32, DD/32), wblk>>>(Wk, wk2, DD, DD);
    convert_w_kernel<<<dim3(DD/32, DD/32), wblk>>>(Wv, wv2, DD, DD);
    convert_w_kernel<<<dim3(DD/32, DD/32), wblk>>>(Wo, wo2, DD, DD);
    convert_a_kernel<<<(int)(((size_t)MM*DD/4 + 255)/256), blk>>>(x, ax, DD);

    // #5: profiled GEMM
    mma_gemm_kernel<<<gD, blk, GEMM_SMEM>>>(ax, wq2, bq, q, DD, 3*DD, 0);
    mma_gemm_kernel<<<gD, blk, GEMM_SMEM>>>(ax, wk2, bk, k, DD, 3*DD, 0);
    mma_gemm_kernel<<<gD, blk, GEMM_SMEM>>>(ax, wv2, bv, v, DD, 3*DD, 0);

    // attention: tensor-core flash, writes split A'' (g_aatt) directly
    attn_tc_kernel<<<dim3(SS/64, BB*HH), 128, ATT2_SMEM>>>(q, k, v, aatt);

    // output projection + residual LN
    mma_gemm_kernel<<<gD, blk, GEMM_SMEM>>>(aatt, wo2, bo, proj, DD, 3*DD, 0);
    add_ln_kernel<<<MM, blk>>>(x, proj, g1, b1, x1);

    // FFN
    convert_w_kernel<<<dim3(FF/32, DD/32), wblk>>>(W1, w12, DD, FF);
    convert_a_kernel<<<(int)(((size_t)MM*DD/4 + 255)/256), blk>>>(x1, ax1, DD);
    mma_gemm_kernel<<<dim3(FF/128, MM/128), blk, GEMM_SMEM>>>(ax1, w12, c1, ff1, FF, 3*DD, 1);
    convert_w_kernel<<<dim3(DD/32, FF/32), wblk>>>(W2, w22, FF, DD);
    convert_a_kernel<<<(int)(((size_t)MM*FF/4 + 255)/256), blk>>>(ff1, aff1, FF);
    mma_gemm_kernel<<<gD, blk, GEMM_SMEM>>>(aff1, w22, c2, ff2, DD, 3*FF, 0);
    add_ln_kernel<<<MM, blk>>>(x1, ff2, g2, b2, out);
}